// round 11
// baseline (speedup 1.0000x reference)
#include <cuda_runtime.h>
#include <cuda_bf16.h>
#include <float.h>
#include <mma.h>

using namespace nvcuda;

#define NNODES 50000
#define NPAD   50048
#define EMAX   800000
#define ETOTMAX (EMAX + NNODES)
#define IN_CH  256
#define HEADS  8
#define HID    32
#define C1     (HEADS*HID)   // 256
#define OUT_CH 64
#define NEG_SLOPE 0.2f
#define CAP 96

// ---------------- scratch ----------------------------------------------------
__device__ float          g_h1 [NPAD*C1];      // x @ W1 (fp32)
__device__ __nv_bfloat16  g_h1b[NPAD*C1];      // bf16 copy for gather
__device__ float          g_o1 [NNODES*C1];    // layer-1 output
__device__ float          g_h2 [NPAD*OUT_CH];  // o1 @ W2 (padded rows)
__device__ float g_as1[NNODES*HEADS];
__device__ float g_ad1[NNODES*HEADS];
__device__ float g_as2[NNODES];
__device__ float g_ad2[NNODES];
__device__ int   g_deg[NNODES];
__device__ int   g_rowptr[NNODES+1];
__device__ int   g_cursor[NNODES];
__device__ int   g_csrc[ETOTMAX];
__device__ int   g_bsums[64];

// ---------------- CSR build --------------------------------------------------
__global__ void fill_int_k(int* __restrict__ p, int v, int n) {
    int i = blockIdx.x*blockDim.x + threadIdx.x;
    if (i < n) p[i] = v;
}

__global__ void hist_k(const int* __restrict__ dst, int* __restrict__ deg, int E) {
    int i = blockIdx.x*blockDim.x + threadIdx.x;
    if (i < E) atomicAdd(&deg[dst[i]], 1);
}

__global__ void bscan_k(const int* __restrict__ deg, int* __restrict__ rowptr,
                        int* __restrict__ bsums, int n) {
    __shared__ int sm[1024];
    int base = blockIdx.x * 1024, tid = threadIdx.x;
    int v = (base + tid < n) ? deg[base + tid] : 0;
    sm[tid] = v;
    __syncthreads();
    for (int off = 1; off < 1024; off <<= 1) {
        int t = (tid >= off) ? sm[tid - off] : 0;
        __syncthreads();
        sm[tid] += t;
        __syncthreads();
    }
    if (base + tid < n) rowptr[base + tid + 1] = sm[tid];
    if (tid == 1023) bsums[blockIdx.x] = sm[1023];
}

__global__ void pscan_k(int* __restrict__ bsums, int nb) {
    __shared__ int sm[64];
    int tid = threadIdx.x;
    sm[tid] = (tid < nb) ? bsums[tid] : 0;
    __syncthreads();
    for (int off = 1; off < 64; off <<= 1) {
        int t = (tid >= off) ? sm[tid - off] : 0;
        __syncthreads();
        sm[tid] += t;
        __syncthreads();
    }
    if (tid < nb) bsums[tid] = sm[tid];
}

// finalize rowptr and also write cursor = rowptr start (no extra memcpy)
__global__ void addoff_k(int* __restrict__ rowptr, int* __restrict__ cursor,
                         const int* __restrict__ bsums, int n) {
    int i = blockIdx.x*blockDim.x + threadIdx.x;
    if (i >= n) return;
    int blk = i >> 10;
    int v = rowptr[i + 1] + (blk > 0 ? bsums[blk - 1] : 0);
    rowptr[i + 1] = v;
    if (i + 1 < n) cursor[i + 1] = v;
    if (i == 0) { rowptr[0] = 0; cursor[0] = 0; }
}

__global__ void scatter_k(const int* __restrict__ src, const int* __restrict__ dst,
                          int* __restrict__ cursor, int* __restrict__ csrc,
                          int Etot, int E) {
    int i = blockIdx.x*blockDim.x + threadIdx.x;
    if (i >= Etot) return;
    int s, d;
    if (i < E) { s = src[i]; d = dst[i]; }
    else       { s = d = i - E; }
    int pos = atomicAdd(&cursor[d], 1);
    csrc[pos] = s;
}

// ---------------- TF32 WMMA GEMM: C[M,N] = A[M,K] @ B[K,N] ------------------
// BM=128, BK=32, 8 warps arranged 2x4. BN=128: warp 64x32 (acc[4][2]);
// BN=64: warp 64x16 (acc[4][1]). C rows padded to multiple of 128.
template<int BN>
__global__ void gemm_tf32(const float* __restrict__ A, const float* __restrict__ B,
                          float* __restrict__ C, int M, int N, int K) {
    const int BM = 128, BK = 32;
    const int WN = BN / 4;           // warp tile in N (32 or 16)
    const int FN = WN / 16;          // frags in N (2 or 1)
    __shared__ float As[BM][BK + 4];
    __shared__ float Bs[BK][BN + 4];
    int tid = threadIdx.x;
    int wid = tid >> 5;
    int wr = wid >> 2, wc = wid & 3;
    int row0 = blockIdx.y * BM, col0 = blockIdx.x * BN;

    wmma::fragment<wmma::accumulator, 16, 16, 8, float> acc[4][FN];
    #pragma unroll
    for (int i = 0; i < 4; i++)
        #pragma unroll
        for (int j = 0; j < FN; j++)
            wmma::fill_fragment(acc[i][j], 0.f);

    for (int k0 = 0; k0 < K; k0 += BK) {
        #pragma unroll
        for (int i = 0; i < 4; i++) {               // A: 128x32 = 1024 float4
            int id = tid + i * 256;
            int r = id >> 3;
            int c4 = (id & 7) * 4;
            int gr = row0 + r;
            float4 v = make_float4(0.f,0.f,0.f,0.f);
            if (gr < M) v = *(const float4*)(A + (size_t)gr * K + k0 + c4);
            *(float4*)&As[r][c4] = v;
        }
        #pragma unroll
        for (int i = 0; i < BN/32; i++) {           // B: 32xBN
            int id = tid + i * 256;
            int r = id / (BN/4);
            int c4 = (id % (BN/4)) * 4;
            float4 v = *(const float4*)(B + (size_t)(k0 + r) * N + col0 + c4);
            *(float4*)&Bs[r][c4] = v;
        }
        __syncthreads();

        #pragma unroll
        for (int kk = 0; kk < BK / 8; kk++) {
            wmma::fragment<wmma::matrix_a, 16, 16, 8, wmma::precision::tf32, wmma::row_major> af[4];
            wmma::fragment<wmma::matrix_b, 16, 16, 8, wmma::precision::tf32, wmma::row_major> bf[FN];
            #pragma unroll
            for (int i = 0; i < 4; i++) {
                wmma::load_matrix_sync(af[i], &As[wr*64 + i*16][kk*8], BK + 4);
                #pragma unroll
                for (int t = 0; t < af[i].num_elements; t++)
                    af[i].x[t] = wmma::__float_to_tf32(af[i].x[t]);
            }
            #pragma unroll
            for (int j = 0; j < FN; j++) {
                wmma::load_matrix_sync(bf[j], &Bs[kk*8][wc*WN + j*16], BN + 4);
                #pragma unroll
                for (int t = 0; t < bf[j].num_elements; t++)
                    bf[j].x[t] = wmma::__float_to_tf32(bf[j].x[t]);
            }
            #pragma unroll
            for (int i = 0; i < 4; i++)
                #pragma unroll
                for (int j = 0; j < FN; j++)
                    wmma::mma_sync(acc[i][j], af[i], bf[j], acc[i][j]);
        }
        __syncthreads();
    }

    #pragma unroll
    for (int i = 0; i < 4; i++)
        #pragma unroll
        for (int j = 0; j < FN; j++) {
            int gr = row0 + wr*64 + i*16;
            wmma::store_matrix_sync(C + (size_t)gr * N + col0 + wc*WN + j*16,
                                    acc[i][j], N, wmma::mem_row_major);
        }
}

// ---------------- attention coeff, layer 1 (+ bf16 convert) ----------------
__global__ void attn1_fused(const float* __restrict__ h,
                            const float* __restrict__ att_s,
                            const float* __restrict__ att_d,
                            float* __restrict__ as, float* __restrict__ ad,
                            __nv_bfloat16* __restrict__ hb, int n) {
    int i = blockIdx.x * blockDim.x + threadIdx.x;
    if (i >= n * HEADS) return;
    int node = i / HEADS, hh = i - node * HEADS;
    const float* row = h + (size_t)node * C1 + hh * HID;
    __nv_bfloat16* brow = hb + (size_t)node * C1 + hh * HID;
    const float* ws = att_s + hh * HID;
    const float* wd = att_d + hh * HID;
    float s = 0.f, d = 0.f;
    #pragma unroll
    for (int f = 0; f < HID; f += 2) {
        float v0 = row[f], v1 = row[f+1];
        s = fmaf(v0, ws[f], s); d = fmaf(v0, wd[f], d);
        s = fmaf(v1, ws[f+1], s); d = fmaf(v1, wd[f+1], d);
        *(__nv_bfloat162*)(brow + f) = __floats2bfloat162_rn(v0, v1);
    }
    as[i] = s;
    ad[i] = d;
}

__global__ void attn_coeff2(const float* __restrict__ h,
                            const float* __restrict__ att_s,
                            const float* __restrict__ att_d,
                            float* __restrict__ as, float* __restrict__ ad, int n) {
    int i = blockIdx.x * blockDim.x + threadIdx.x;
    if (i >= n) return;
    const float* row = h + (size_t)i * OUT_CH;
    float s = 0.f, d = 0.f;
    #pragma unroll 8
    for (int f = 0; f < OUT_CH; f++) {
        float v = row[f];
        s = fmaf(v, att_s[f], s);
        d = fmaf(v, att_d[f], d);
    }
    as[i] = s;
    ad[i] = d;
}

// ---------------- fused per-node softmax + aggregation, layer 1 -------------
__global__ void node_l1(const int* __restrict__ rowptr, const int* __restrict__ csrc,
                        const float* __restrict__ as, const float* __restrict__ ad,
                        const __nv_bfloat16* __restrict__ hb,
                        const float* __restrict__ bias,
                        float* __restrict__ out, int n) {
    __shared__ float buf[8][8][CAP];
    int w = threadIdx.x >> 5, lane = threadIdx.x & 31;
    int node = blockIdx.x * 8 + w;
    if (node >= n) return;
    int r0 = rowptr[node];
    int deg = rowptr[node+1] - r0;
    int g = lane >> 2, li = lane & 3;
    float ad_h = ad[node*8 + g];

    float mymax = -FLT_MAX;
    for (int k = li; k < deg; k += 4) {
        int s = csrc[r0 + k];
        float e = as[s*8 + g] + ad_h;
        e = e > 0.f ? e : NEG_SLOPE * e;
        if (k < CAP) buf[w][g][k] = e;
        mymax = fmaxf(mymax, e);
    }
    mymax = fmaxf(mymax, __shfl_xor_sync(0xffffffffu, mymax, 1));
    mymax = fmaxf(mymax, __shfl_xor_sync(0xffffffffu, mymax, 2));
    __syncwarp();

    float sum = 0.f;
    for (int k = li; k < deg; k += 4) {
        float e;
        if (k < CAP) e = buf[w][g][k];
        else {
            int s = csrc[r0 + k];
            e = as[s*8 + g] + ad_h;
            e = e > 0.f ? e : NEG_SLOPE * e;
        }
        float x = __expf(e - mymax);
        if (k < CAP) buf[w][g][k] = x;
        sum += x;
    }
    sum += __shfl_xor_sync(0xffffffffu, sum, 1);
    sum += __shfl_xor_sync(0xffffffffu, sum, 2);
    float invden = 1.f / sum;
    __syncwarp();

    float acc[8] = {};
    for (int base = 0; base < deg; base += 32) {
        int myS = (base + lane < deg) ? csrc[r0 + base + lane] : 0;
        int kmax = min(32, deg - base);
        int kk = 0;
        for (; kk + 1 < kmax; kk += 2) {
            int k0i = base + kk, k1i = base + kk + 1;
            int s0 = __shfl_sync(0xffffffffu, myS, kk);
            int s1 = __shfl_sync(0xffffffffu, myS, kk + 1);
            uint4 r0v = *(const uint4*)(hb + (size_t)s0*C1 + lane*8);
            uint4 r1v = *(const uint4*)(hb + (size_t)s1*C1 + lane*8);
            float a0, a1;
            if (k0i < CAP) a0 = buf[w][g][k0i] * invden;
            else {
                float e = as[s0*8 + g] + ad_h;
                e = e > 0.f ? e : NEG_SLOPE * e;
                a0 = __expf(e - mymax) * invden;
            }
            if (k1i < CAP) a1 = buf[w][g][k1i] * invden;
            else {
                float e = as[s1*8 + g] + ad_h;
                e = e > 0.f ? e : NEG_SLOPE * e;
                a1 = __expf(e - mymax) * invden;
            }
            const unsigned* u0 = &r0v.x;
            const unsigned* u1 = &r1v.x;
            #pragma unroll
            for (int q = 0; q < 4; q++) {
                float2 f0 = __bfloat1622float2(*(const __nv_bfloat162*)&u0[q]);
                float2 f1 = __bfloat1622float2(*(const __nv_bfloat162*)&u1[q]);
                acc[q*2+0] = fmaf(a0, f0.x, acc[q*2+0]);
                acc[q*2+1] = fmaf(a0, f0.y, acc[q*2+1]);
                acc[q*2+0] = fmaf(a1, f1.x, acc[q*2+0]);
                acc[q*2+1] = fmaf(a1, f1.y, acc[q*2+1]);
            }
        }
        if (kk < kmax) {
            int ki = base + kk;
            int s = __shfl_sync(0xffffffffu, myS, kk);
            uint4 rv = *(const uint4*)(hb + (size_t)s*C1 + lane*8);
            float a;
            if (ki < CAP) a = buf[w][g][ki] * invden;
            else {
                float e = as[s*8 + g] + ad_h;
                e = e > 0.f ? e : NEG_SLOPE * e;
                a = __expf(e - mymax) * invden;
            }
            const unsigned* u = &rv.x;
            #pragma unroll
            for (int q = 0; q < 4; q++) {
                float2 f = __bfloat1622float2(*(const __nv_bfloat162*)&u[q]);
                acc[q*2+0] = fmaf(a, f.x, acc[q*2+0]);
                acc[q*2+1] = fmaf(a, f.y, acc[q*2+1]);
            }
        }
    }
    float4 o0, o1;
    const float4* bp = (const float4*)(bias + lane*8);
    float4 b0 = bp[0], b1 = bp[1];
    o0.x = fmaxf(acc[0] + b0.x, 0.f); o0.y = fmaxf(acc[1] + b0.y, 0.f);
    o0.z = fmaxf(acc[2] + b0.z, 0.f); o0.w = fmaxf(acc[3] + b0.w, 0.f);
    o1.x = fmaxf(acc[4] + b1.x, 0.f); o1.y = fmaxf(acc[5] + b1.y, 0.f);
    o1.z = fmaxf(acc[6] + b1.z, 0.f); o1.w = fmaxf(acc[7] + b1.w, 0.f);
    float4* op = (float4*)(out + (size_t)node*C1 + lane*8);
    op[0] = o0; op[1] = o1;
}

// ---------------- fused per-node softmax + aggregation, layer 2 -------------
__global__ void node_l2(const int* __restrict__ rowptr, const int* __restrict__ csrc,
                        const float* __restrict__ as, const float* __restrict__ ad,
                        const float* __restrict__ h, const float* __restrict__ bias,
                        float* __restrict__ out, int n) {
    __shared__ float buf[8][CAP];
    int w = threadIdx.x >> 5, lane = threadIdx.x & 31;
    int node = blockIdx.x * 8 + w;
    if (node >= n) return;
    int r0 = rowptr[node];
    int deg = rowptr[node+1] - r0;
    float ad_h = ad[node];

    float mymax = -FLT_MAX;
    for (int k = lane; k < deg; k += 32) {
        int s = csrc[r0 + k];
        float e = as[s] + ad_h;
        e = e > 0.f ? e : NEG_SLOPE * e;
        if (k < CAP) buf[w][k] = e;
        mymax = fmaxf(mymax, e);
    }
    #pragma unroll
    for (int m = 1; m < 32; m <<= 1)
        mymax = fmaxf(mymax, __shfl_xor_sync(0xffffffffu, mymax, m));
    __syncwarp();

    float sum = 0.f;
    for (int k = lane; k < deg; k += 32) {
        float e;
        if (k < CAP) e = buf[w][k];
        else {
            int s = csrc[r0 + k];
            e = as[s] + ad_h;
            e = e > 0.f ? e : NEG_SLOPE * e;
        }
        float x = __expf(e - mymax);
        if (k < CAP) buf[w][k] = x;
        sum += x;
    }
    #pragma unroll
    for (int m = 1; m < 32; m <<= 1)
        sum += __shfl_xor_sync(0xffffffffu, sum, m);
    float invden = 1.f / sum;
    __syncwarp();

    float2 acc = make_float2(0.f, 0.f);
    for (int base = 0; base < deg; base += 32) {
        int myS = (base + lane < deg) ? csrc[r0 + base + lane] : 0;
        int kmax = min(32, deg - base);
        int kk = 0;
        for (; kk + 1 < kmax; kk += 2) {
            int k0i = base + kk, k1i = base + kk + 1;
            int s0 = __shfl_sync(0xffffffffu, myS, kk);
            int s1 = __shfl_sync(0xffffffffu, myS, kk + 1);
            float2 v0 = *(const float2*)(h + (size_t)s0*OUT_CH + lane*2);
            float2 v1 = *(const float2*)(h + (size_t)s1*OUT_CH + lane*2);
            float a0, a1;
            if (k0i < CAP) a0 = buf[w][k0i] * invden;
            else {
                float e = as[s0] + ad_h;
                e = e > 0.f ? e : NEG_SLOPE * e;
                a0 = __expf(e - mymax) * invden;
            }
            if (k1i < CAP) a1 = buf[w][k1i] * invden;
            else {
                float e = as[s1] + ad_h;
                e = e > 0.f ? e : NEG_SLOPE * e;
                a1 = __expf(e - mymax) * invden;
            }
            acc.x = fmaf(a0, v0.x, acc.x); acc.y = fmaf(a0, v0.y, acc.y);
            acc.x = fmaf(a1, v1.x, acc.x); acc.y = fmaf(a1, v1.y, acc.y);
        }
        if (kk < kmax) {
            int ki = base + kk;
            int s = __shfl_sync(0xffffffffu, myS, kk);
            float2 v = *(const float2*)(h + (size_t)s*OUT_CH + lane*2);
            float a;
            if (ki < CAP) a = buf[w][ki] * invden;
            else {
                float e = as[s] + ad_h;
                e = e > 0.f ? e : NEG_SLOPE * e;
                a = __expf(e - mymax) * invden;
            }
            acc.x = fmaf(a, v.x, acc.x); acc.y = fmaf(a, v.y, acc.y);
        }
    }
    acc.x += bias[lane*2];
    acc.y += bias[lane*2+1];
    *(float2*)(out + (size_t)node*OUT_CH + lane*2) = acc;
}

// ---------------- launch ----------------------------------------------------
extern "C" void kernel_launch(void* const* d_in, const int* in_sizes, int n_in,
                              void* d_out, int out_size) {
    const float* x      = (const float*)d_in[0];
    const int*   ei     = (const int*)d_in[1];
    const float* W1     = (const float*)d_in[2];
    const float* att_s1 = (const float*)d_in[3];
    const float* att_d1 = (const float*)d_in[4];
    const float* b1     = (const float*)d_in[5];
    const float* W2     = (const float*)d_in[6];
    const float* att_s2 = (const float*)d_in[7];
    const float* att_d2 = (const float*)d_in[8];
    const float* b2     = (const float*)d_in[9];
    float* out = (float*)d_out;

    int n    = in_sizes[0] / IN_CH;   // 50000
    int E    = in_sizes[1] / 2;       // 800000
    int Etot = E + n;
    const int* src = ei;
    const int* dst = ei + E;

    float *h1, *o1, *h2, *as1, *ad1, *as2, *ad2;
    __nv_bfloat16* h1b;
    int *deg, *rowptr, *cursor, *csrc, *bsums;
    cudaGetSymbolAddress((void**)&h1,     g_h1);
    cudaGetSymbolAddress((void**)&h1b,    g_h1b);
    cudaGetSymbolAddress((void**)&o1,     g_o1);
    cudaGetSymbolAddress((void**)&h2,     g_h2);
    cudaGetSymbolAddress((void**)&as1,    g_as1);
    cudaGetSymbolAddress((void**)&ad1,    g_ad1);
    cudaGetSymbolAddress((void**)&as2,    g_as2);
    cudaGetSymbolAddress((void**)&ad2,    g_ad2);
    cudaGetSymbolAddress((void**)&deg,    g_deg);
    cudaGetSymbolAddress((void**)&rowptr, g_rowptr);
    cudaGetSymbolAddress((void**)&cursor, g_cursor);
    cudaGetSymbolAddress((void**)&csrc,   g_csrc);
    cudaGetSymbolAddress((void**)&bsums,  g_bsums);

    int nb = (n + 1023) / 1024;

    // ---- CSR build ----
    fill_int_k<<<(n + 255)/256, 256>>>(deg, 1, n);   // self-loop baked in
    hist_k<<<(E + 255)/256, 256>>>(dst, deg, E);
    bscan_k<<<nb, 1024>>>(deg, rowptr, bsums, n);
    pscan_k<<<1, 64>>>(bsums, nb);
    addoff_k<<<(n + 255)/256, 256>>>(rowptr, cursor, bsums, n);
    scatter_k<<<(Etot + 255)/256, 256>>>(src, dst, cursor, csrc, Etot, E);

    // ---- layer 1 ----
    {
        dim3 grid(C1/128, (n + 127)/128);
        gemm_tf32<128><<<grid, 256>>>(x, W1, h1, n, C1, IN_CH);
    }
    attn1_fused<<<(n*HEADS + 255)/256, 256>>>(h1, att_s1, att_d1, as1, ad1, h1b, n);
    node_l1<<<(n + 7)/8, 256>>>(rowptr, csrc, as1, ad1, h1b, b1, o1, n);

    // ---- layer 2 ----
    {
        dim3 grid(OUT_CH/64, (n + 127)/128);
        gemm_tf32<64><<<grid, 256>>>(o1, W2, h2, n, OUT_CH, C1);
    }
    attn_coeff2<<<(n + 255)/256, 256>>>(h2, att_s2, att_d2, as2, ad2, n);
    node_l2<<<(n + 7)/8, 256>>>(rowptr, csrc, as2, ad2, h2, b2, out, n);
}

// round 12
// speedup vs baseline: 1.0137x; 1.0137x over previous
#include <cuda_runtime.h>
#include <cuda_bf16.h>
#include <float.h>
#include <mma.h>

using namespace nvcuda;

#define NNODES 50000
#define NPAD   50048
#define EMAX   800000
#define ETOTMAX (EMAX + NNODES)
#define IN_CH  256
#define HEADS  8
#define HID    32
#define C1     (HEADS*HID)   // 256
#define OUT_CH 64
#define NEG_SLOPE 0.2f
#define CAP 96

// ---------------- scratch ----------------------------------------------------
__device__ float          g_h1 [NPAD*C1];      // x @ W1 (fp32)
__device__ __nv_bfloat16  g_h1b[NPAD*C1];      // bf16 copy for gather
__device__ float          g_o1 [NNODES*C1];    // layer-1 output
__device__ float          g_h2 [NPAD*OUT_CH];  // o1 @ W2 (padded rows)
__device__ float g_as1[NNODES*HEADS];
__device__ float g_ad1[NNODES*HEADS];
__device__ float g_as2[NNODES];
__device__ float g_ad2[NNODES];
__device__ int   g_deg[NNODES];
__device__ int   g_rowptr[NNODES+1];
__device__ int   g_cursor[NNODES];
__device__ int   g_csrc[ETOTMAX];
__device__ int   g_bsums[64];

// ---------------- CSR build --------------------------------------------------
__global__ void fill_int_k(int* __restrict__ p, int v, int n) {
    int i = blockIdx.x*blockDim.x + threadIdx.x;
    if (i < n) p[i] = v;
}

__global__ void hist_k(const int* __restrict__ dst, int* __restrict__ deg, int E) {
    int i = blockIdx.x*blockDim.x + threadIdx.x;
    if (i < E) atomicAdd(&deg[dst[i]], 1);
}

__global__ void bscan_k(const int* __restrict__ deg, int* __restrict__ rowptr,
                        int* __restrict__ bsums, int n) {
    __shared__ int sm[1024];
    int base = blockIdx.x * 1024, tid = threadIdx.x;
    int v = (base + tid < n) ? deg[base + tid] : 0;
    sm[tid] = v;
    __syncthreads();
    for (int off = 1; off < 1024; off <<= 1) {
        int t = (tid >= off) ? sm[tid - off] : 0;
        __syncthreads();
        sm[tid] += t;
        __syncthreads();
    }
    if (base + tid < n) rowptr[base + tid + 1] = sm[tid];
    if (tid == 1023) bsums[blockIdx.x] = sm[1023];
}

__global__ void pscan_k(int* __restrict__ bsums, int nb) {
    __shared__ int sm[64];
    int tid = threadIdx.x;
    sm[tid] = (tid < nb) ? bsums[tid] : 0;
    __syncthreads();
    for (int off = 1; off < 64; off <<= 1) {
        int t = (tid >= off) ? sm[tid - off] : 0;
        __syncthreads();
        sm[tid] += t;
        __syncthreads();
    }
    if (tid < nb) bsums[tid] = sm[tid];
}

// finalize rowptr and also write cursor = rowptr start (no extra memcpy)
__global__ void addoff_k(int* __restrict__ rowptr, int* __restrict__ cursor,
                         const int* __restrict__ bsums, int n) {
    int i = blockIdx.x*blockDim.x + threadIdx.x;
    if (i >= n) return;
    int blk = i >> 10;
    int v = rowptr[i + 1] + (blk > 0 ? bsums[blk - 1] : 0);
    rowptr[i + 1] = v;
    if (i + 1 < n) cursor[i + 1] = v;
    if (i == 0) { rowptr[0] = 0; cursor[0] = 0; }
}

__global__ void scatter_k(const int* __restrict__ src, const int* __restrict__ dst,
                          int* __restrict__ cursor, int* __restrict__ csrc,
                          int Etot, int E) {
    int i = blockIdx.x*blockDim.x + threadIdx.x;
    if (i >= Etot) return;
    int s, d;
    if (i < E) { s = src[i]; d = dst[i]; }
    else       { s = d = i - E; }
    int pos = atomicAdd(&cursor[d], 1);
    csrc[pos] = s;
}

// ---------------- TF32 WMMA GEMM: C[M,N] = A[M,K] @ B[K,N] ------------------
// BM=128, BK=32, 8 warps arranged 2x4. BN=128: warp 64x32 (acc[4][2]);
// BN=64: warp 64x16 (acc[4][1]). C rows padded to multiple of 128.
template<int BN>
__global__ void gemm_tf32(const float* __restrict__ A, const float* __restrict__ B,
                          float* __restrict__ C, int M, int N, int K) {
    const int BM = 128, BK = 32;
    const int WN = BN / 4;           // warp tile in N (32 or 16)
    const int FN = WN / 16;          // frags in N (2 or 1)
    __shared__ float As[BM][BK + 4];
    __shared__ float Bs[BK][BN + 4];
    int tid = threadIdx.x;
    int wid = tid >> 5;
    int wr = wid >> 2, wc = wid & 3;
    int row0 = blockIdx.y * BM, col0 = blockIdx.x * BN;

    wmma::fragment<wmma::accumulator, 16, 16, 8, float> acc[4][FN];
    #pragma unroll
    for (int i = 0; i < 4; i++)
        #pragma unroll
        for (int j = 0; j < FN; j++)
            wmma::fill_fragment(acc[i][j], 0.f);

    for (int k0 = 0; k0 < K; k0 += BK) {
        #pragma unroll
        for (int i = 0; i < 4; i++) {               // A: 128x32 = 1024 float4
            int id = tid + i * 256;
            int r = id >> 3;
            int c4 = (id & 7) * 4;
            int gr = row0 + r;
            float4 v = make_float4(0.f,0.f,0.f,0.f);
            if (gr < M) v = *(const float4*)(A + (size_t)gr * K + k0 + c4);
            *(float4*)&As[r][c4] = v;
        }
        #pragma unroll
        for (int i = 0; i < BN/32; i++) {           // B: 32xBN
            int id = tid + i * 256;
            int r = id / (BN/4);
            int c4 = (id % (BN/4)) * 4;
            float4 v = *(const float4*)(B + (size_t)(k0 + r) * N + col0 + c4);
            *(float4*)&Bs[r][c4] = v;
        }
        __syncthreads();

        #pragma unroll
        for (int kk = 0; kk < BK / 8; kk++) {
            wmma::fragment<wmma::matrix_a, 16, 16, 8, wmma::precision::tf32, wmma::row_major> af[4];
            wmma::fragment<wmma::matrix_b, 16, 16, 8, wmma::precision::tf32, wmma::row_major> bf[FN];
            #pragma unroll
            for (int i = 0; i < 4; i++) {
                wmma::load_matrix_sync(af[i], &As[wr*64 + i*16][kk*8], BK + 4);
                #pragma unroll
                for (int t = 0; t < af[i].num_elements; t++)
                    af[i].x[t] = wmma::__float_to_tf32(af[i].x[t]);
            }
            #pragma unroll
            for (int j = 0; j < FN; j++) {
                wmma::load_matrix_sync(bf[j], &Bs[kk*8][wc*WN + j*16], BN + 4);
                #pragma unroll
                for (int t = 0; t < bf[j].num_elements; t++)
                    bf[j].x[t] = wmma::__float_to_tf32(bf[j].x[t]);
            }
            #pragma unroll
            for (int i = 0; i < 4; i++)
                #pragma unroll
                for (int j = 0; j < FN; j++)
                    wmma::mma_sync(acc[i][j], af[i], bf[j], acc[i][j]);
        }
        __syncthreads();
    }

    #pragma unroll
    for (int i = 0; i < 4; i++)
        #pragma unroll
        for (int j = 0; j < FN; j++) {
            int gr = row0 + wr*64 + i*16;
            wmma::store_matrix_sync(C + (size_t)gr * N + col0 + wc*WN + j*16,
                                    acc[i][j], N, wmma::mem_row_major);
        }
}

// ---------------- attention coeff, layer 1 (+ bf16 convert) ----------------
__global__ void attn1_fused(const float* __restrict__ h,
                            const float* __restrict__ att_s,
                            const float* __restrict__ att_d,
                            float* __restrict__ as, float* __restrict__ ad,
                            __nv_bfloat16* __restrict__ hb, int n) {
    int i = blockIdx.x * blockDim.x + threadIdx.x;
    if (i >= n * HEADS) return;
    int node = i / HEADS, hh = i - node * HEADS;
    const float* row = h + (size_t)node * C1 + hh * HID;
    __nv_bfloat16* brow = hb + (size_t)node * C1 + hh * HID;
    const float* ws = att_s + hh * HID;
    const float* wd = att_d + hh * HID;
    float s = 0.f, d = 0.f;
    #pragma unroll
    for (int f = 0; f < HID; f += 2) {
        float v0 = row[f], v1 = row[f+1];
        s = fmaf(v0, ws[f], s); d = fmaf(v0, wd[f], d);
        s = fmaf(v1, ws[f+1], s); d = fmaf(v1, wd[f+1], d);
        *(__nv_bfloat162*)(brow + f) = __floats2bfloat162_rn(v0, v1);
    }
    as[i] = s;
    ad[i] = d;
}

__global__ void attn_coeff2(const float* __restrict__ h,
                            const float* __restrict__ att_s,
                            const float* __restrict__ att_d,
                            float* __restrict__ as, float* __restrict__ ad, int n) {
    int i = blockIdx.x * blockDim.x + threadIdx.x;
    if (i >= n) return;
    const float* row = h + (size_t)i * OUT_CH;
    float s = 0.f, d = 0.f;
    #pragma unroll 8
    for (int f = 0; f < OUT_CH; f++) {
        float v = row[f];
        s = fmaf(v, att_s[f], s);
        d = fmaf(v, att_d[f], d);
    }
    as[i] = s;
    ad[i] = d;
}

// ---------------- fused per-node softmax + aggregation, layer 1 -------------
__global__ void node_l1(const int* __restrict__ rowptr, const int* __restrict__ csrc,
                        const float* __restrict__ as, const float* __restrict__ ad,
                        const __nv_bfloat16* __restrict__ hb,
                        const float* __restrict__ bias,
                        float* __restrict__ out, int n) {
    __shared__ float buf[8][8][CAP];
    int w = threadIdx.x >> 5, lane = threadIdx.x & 31;
    int node = blockIdx.x * 8 + w;
    if (node >= n) return;
    int r0 = rowptr[node];
    int deg = rowptr[node+1] - r0;
    int g = lane >> 2, li = lane & 3;
    float ad_h = ad[node*8 + g];

    float mymax = -FLT_MAX;
    for (int k = li; k < deg; k += 4) {
        int s = csrc[r0 + k];
        float e = as[s*8 + g] + ad_h;
        e = e > 0.f ? e : NEG_SLOPE * e;
        if (k < CAP) buf[w][g][k] = e;
        mymax = fmaxf(mymax, e);
    }
    mymax = fmaxf(mymax, __shfl_xor_sync(0xffffffffu, mymax, 1));
    mymax = fmaxf(mymax, __shfl_xor_sync(0xffffffffu, mymax, 2));
    __syncwarp();

    float sum = 0.f;
    for (int k = li; k < deg; k += 4) {
        float e;
        if (k < CAP) e = buf[w][g][k];
        else {
            int s = csrc[r0 + k];
            e = as[s*8 + g] + ad_h;
            e = e > 0.f ? e : NEG_SLOPE * e;
        }
        float x = __expf(e - mymax);
        if (k < CAP) buf[w][g][k] = x;
        sum += x;
    }
    sum += __shfl_xor_sync(0xffffffffu, sum, 1);
    sum += __shfl_xor_sync(0xffffffffu, sum, 2);
    float invden = 1.f / sum;
    __syncwarp();

    float acc[8] = {};
    for (int base = 0; base < deg; base += 32) {
        int myS = (base + lane < deg) ? csrc[r0 + base + lane] : 0;
        int kmax = min(32, deg - base);
        int kk = 0;
        for (; kk + 1 < kmax; kk += 2) {
            int k0i = base + kk, k1i = base + kk + 1;
            int s0 = __shfl_sync(0xffffffffu, myS, kk);
            int s1 = __shfl_sync(0xffffffffu, myS, kk + 1);
            uint4 r0v = *(const uint4*)(hb + (size_t)s0*C1 + lane*8);
            uint4 r1v = *(const uint4*)(hb + (size_t)s1*C1 + lane*8);
            float a0, a1;
            if (k0i < CAP) a0 = buf[w][g][k0i] * invden;
            else {
                float e = as[s0*8 + g] + ad_h;
                e = e > 0.f ? e : NEG_SLOPE * e;
                a0 = __expf(e - mymax) * invden;
            }
            if (k1i < CAP) a1 = buf[w][g][k1i] * invden;
            else {
                float e = as[s1*8 + g] + ad_h;
                e = e > 0.f ? e : NEG_SLOPE * e;
                a1 = __expf(e - mymax) * invden;
            }
            const unsigned* u0 = &r0v.x;
            const unsigned* u1 = &r1v.x;
            #pragma unroll
            for (int q = 0; q < 4; q++) {
                float2 f0 = __bfloat1622float2(*(const __nv_bfloat162*)&u0[q]);
                float2 f1 = __bfloat1622float2(*(const __nv_bfloat162*)&u1[q]);
                acc[q*2+0] = fmaf(a0, f0.x, acc[q*2+0]);
                acc[q*2+1] = fmaf(a0, f0.y, acc[q*2+1]);
                acc[q*2+0] = fmaf(a1, f1.x, acc[q*2+0]);
                acc[q*2+1] = fmaf(a1, f1.y, acc[q*2+1]);
            }
        }
        if (kk < kmax) {
            int ki = base + kk;
            int s = __shfl_sync(0xffffffffu, myS, kk);
            uint4 rv = *(const uint4*)(hb + (size_t)s*C1 + lane*8);
            float a;
            if (ki < CAP) a = buf[w][g][ki] * invden;
            else {
                float e = as[s*8 + g] + ad_h;
                e = e > 0.f ? e : NEG_SLOPE * e;
                a = __expf(e - mymax) * invden;
            }
            const unsigned* u = &rv.x;
            #pragma unroll
            for (int q = 0; q < 4; q++) {
                float2 f = __bfloat1622float2(*(const __nv_bfloat162*)&u[q]);
                acc[q*2+0] = fmaf(a, f.x, acc[q*2+0]);
                acc[q*2+1] = fmaf(a, f.y, acc[q*2+1]);
            }
        }
    }
    float4 o0, o1;
    const float4* bp = (const float4*)(bias + lane*8);
    float4 b0 = bp[0], b1 = bp[1];
    o0.x = fmaxf(acc[0] + b0.x, 0.f); o0.y = fmaxf(acc[1] + b0.y, 0.f);
    o0.z = fmaxf(acc[2] + b0.z, 0.f); o0.w = fmaxf(acc[3] + b0.w, 0.f);
    o1.x = fmaxf(acc[4] + b1.x, 0.f); o1.y = fmaxf(acc[5] + b1.y, 0.f);
    o1.z = fmaxf(acc[6] + b1.z, 0.f); o1.w = fmaxf(acc[7] + b1.w, 0.f);
    float4* op = (float4*)(out + (size_t)node*C1 + lane*8);
    op[0] = o0; op[1] = o1;
}

// ---------------- fused per-node softmax + aggregation, layer 2 -------------
__global__ void node_l2(const int* __restrict__ rowptr, const int* __restrict__ csrc,
                        const float* __restrict__ as, const float* __restrict__ ad,
                        const float* __restrict__ h, const float* __restrict__ bias,
                        float* __restrict__ out, int n) {
    __shared__ float buf[8][CAP];
    int w = threadIdx.x >> 5, lane = threadIdx.x & 31;
    int node = blockIdx.x * 8 + w;
    if (node >= n) return;
    int r0 = rowptr[node];
    int deg = rowptr[node+1] - r0;
    float ad_h = ad[node];

    float mymax = -FLT_MAX;
    for (int k = lane; k < deg; k += 32) {
        int s = csrc[r0 + k];
        float e = as[s] + ad_h;
        e = e > 0.f ? e : NEG_SLOPE * e;
        if (k < CAP) buf[w][k] = e;
        mymax = fmaxf(mymax, e);
    }
    #pragma unroll
    for (int m = 1; m < 32; m <<= 1)
        mymax = fmaxf(mymax, __shfl_xor_sync(0xffffffffu, mymax, m));
    __syncwarp();

    float sum = 0.f;
    for (int k = lane; k < deg; k += 32) {
        float e;
        if (k < CAP) e = buf[w][k];
        else {
            int s = csrc[r0 + k];
            e = as[s] + ad_h;
            e = e > 0.f ? e : NEG_SLOPE * e;
        }
        float x = __expf(e - mymax);
        if (k < CAP) buf[w][k] = x;
        sum += x;
    }
    #pragma unroll
    for (int m = 1; m < 32; m <<= 1)
        sum += __shfl_xor_sync(0xffffffffu, sum, m);
    float invden = 1.f / sum;
    __syncwarp();

    float2 acc = make_float2(0.f, 0.f);
    for (int base = 0; base < deg; base += 32) {
        int myS = (base + lane < deg) ? csrc[r0 + base + lane] : 0;
        int kmax = min(32, deg - base);
        int kk = 0;
        for (; kk + 1 < kmax; kk += 2) {
            int k0i = base + kk, k1i = base + kk + 1;
            int s0 = __shfl_sync(0xffffffffu, myS, kk);
            int s1 = __shfl_sync(0xffffffffu, myS, kk + 1);
            float2 v0 = *(const float2*)(h + (size_t)s0*OUT_CH + lane*2);
            float2 v1 = *(const float2*)(h + (size_t)s1*OUT_CH + lane*2);
            float a0, a1;
            if (k0i < CAP) a0 = buf[w][k0i] * invden;
            else {
                float e = as[s0] + ad_h;
                e = e > 0.f ? e : NEG_SLOPE * e;
                a0 = __expf(e - mymax) * invden;
            }
            if (k1i < CAP) a1 = buf[w][k1i] * invden;
            else {
                float e = as[s1] + ad_h;
                e = e > 0.f ? e : NEG_SLOPE * e;
                a1 = __expf(e - mymax) * invden;
            }
            acc.x = fmaf(a0, v0.x, acc.x); acc.y = fmaf(a0, v0.y, acc.y);
            acc.x = fmaf(a1, v1.x, acc.x); acc.y = fmaf(a1, v1.y, acc.y);
        }
        if (kk < kmax) {
            int ki = base + kk;
            int s = __shfl_sync(0xffffffffu, myS, kk);
            float2 v = *(const float2*)(h + (size_t)s*OUT_CH + lane*2);
            float a;
            if (ki < CAP) a = buf[w][ki] * invden;
            else {
                float e = as[s] + ad_h;
                e = e > 0.f ? e : NEG_SLOPE * e;
                a = __expf(e - mymax) * invden;
            }
            acc.x = fmaf(a, v.x, acc.x); acc.y = fmaf(a, v.y, acc.y);
        }
    }
    acc.x += bias[lane*2];
    acc.y += bias[lane*2+1];
    *(float2*)(out + (size_t)node*OUT_CH + lane*2) = acc;
}

// ---------------- launch ----------------------------------------------------
extern "C" void kernel_launch(void* const* d_in, const int* in_sizes, int n_in,
                              void* d_out, int out_size) {
    const float* x      = (const float*)d_in[0];
    const int*   ei     = (const int*)d_in[1];
    const float* W1     = (const float*)d_in[2];
    const float* att_s1 = (const float*)d_in[3];
    const float* att_d1 = (const float*)d_in[4];
    const float* b1     = (const float*)d_in[5];
    const float* W2     = (const float*)d_in[6];
    const float* att_s2 = (const float*)d_in[7];
    const float* att_d2 = (const float*)d_in[8];
    const float* b2     = (const float*)d_in[9];
    float* out = (float*)d_out;

    int n    = in_sizes[0] / IN_CH;   // 50000
    int E    = in_sizes[1] / 2;       // 800000
    int Etot = E + n;
    const int* src = ei;
    const int* dst = ei + E;

    float *h1, *o1, *h2, *as1, *ad1, *as2, *ad2;
    __nv_bfloat16* h1b;
    int *deg, *rowptr, *cursor, *csrc, *bsums;
    cudaGetSymbolAddress((void**)&h1,     g_h1);
    cudaGetSymbolAddress((void**)&h1b,    g_h1b);
    cudaGetSymbolAddress((void**)&o1,     g_o1);
    cudaGetSymbolAddress((void**)&h2,     g_h2);
    cudaGetSymbolAddress((void**)&as1,    g_as1);
    cudaGetSymbolAddress((void**)&ad1,    g_ad1);
    cudaGetSymbolAddress((void**)&as2,    g_as2);
    cudaGetSymbolAddress((void**)&ad2,    g_ad2);
    cudaGetSymbolAddress((void**)&deg,    g_deg);
    cudaGetSymbolAddress((void**)&rowptr, g_rowptr);
    cudaGetSymbolAddress((void**)&cursor, g_cursor);
    cudaGetSymbolAddress((void**)&csrc,   g_csrc);
    cudaGetSymbolAddress((void**)&bsums,  g_bsums);

    int nb = (n + 1023) / 1024;

    // ---- CSR build ----
    fill_int_k<<<(n + 255)/256, 256>>>(deg, 1, n);   // self-loop baked in
    hist_k<<<(E + 255)/256, 256>>>(dst, deg, E);
    bscan_k<<<nb, 1024>>>(deg, rowptr, bsums, n);
    pscan_k<<<1, 64>>>(bsums, nb);
    addoff_k<<<(n + 255)/256, 256>>>(rowptr, cursor, bsums, n);
    scatter_k<<<(Etot + 255)/256, 256>>>(src, dst, cursor, csrc, Etot, E);

    // ---- layer 1 ----
    {
        dim3 grid(C1/128, (n + 127)/128);
        gemm_tf32<128><<<grid, 256>>>(x, W1, h1, n, C1, IN_CH);
    }
    attn1_fused<<<(n*HEADS + 255)/256, 256>>>(h1, att_s1, att_d1, as1, ad1, h1b, n);
    node_l1<<<(n + 7)/8, 256>>>(rowptr, csrc, as1, ad1, h1b, b1, o1, n);

    // ---- layer 2 ----
    {
        dim3 grid(OUT_CH/64, (n + 127)/128);
        gemm_tf32<64><<<grid, 256>>>(o1, W2, h2, n, OUT_CH, C1);
    }
    attn_coeff2<<<(n + 255)/256, 256>>>(h2, att_s2, att_d2, as2, ad2, n);
    node_l2<<<(n + 7)/8, 256>>>(rowptr, csrc, as2, ad2, h2, b2, out, n);
}